// round 8
// baseline (speedup 1.0000x reference)
#include <cuda_runtime.h>
#include <cuda_fp16.h>
#include <math_constants.h>

// ---------------------------------------------------------------------------
// Quantization4bit, single persistent kernel:
//   phase 1: per-block min/max partials (grid-stride, float4, unroll-4)
//   grid barrier: monotonic counter/epoch (replay-safe)
//   phase 2: affine normalize + nearest-codebook via a 256-cell LUT holding
//            half2(c_lo, c_hi), REPLICATED x32 in shared memory so that
//            addr = cell*32 + lane -> bank = lane: zero bank conflicts for
//            any data distribution. Midpoint recomputed as 0.5f*(lo+hi) --
//            identical fp32 ops/inputs as the original chain => bit-exact
//            (fp32 |.| argmin, first-min tie-break).
// 888 blocks x 256 thr, 6 blocks/SM co-resident (launch_bounds + 32KB smem
// per block, 192KB/SM <= 228KB) => spin barrier safe.
// ---------------------------------------------------------------------------

#define MAX_CB 16
#define NBLK 888
#define NTHR 256
#define NCELL 256

__device__ float g_pmin[NBLK];
__device__ float g_pmax[NBLK];
__device__ float g_final_min;
__device__ float g_final_max;
__device__ unsigned g_counter = 0;   // monotonic arrivals (never reset)
__device__ unsigned g_release = 0;   // monotonic release epoch

__device__ __forceinline__ int cell_of(float xn) {
    float u = fmaf(xn, (float)(NCELL / 2), (float)(NCELL / 2));  // >= 0 by construction
    u = fminf(u, (float)(NCELL - 1));
    return (int)u;
}

__device__ __forceinline__ float lut_pick(unsigned e, float xn) {
    float lo = __half2float(__ushort_as_half((unsigned short)(e & 0xFFFFu)));
    float hi = __half2float(__ushort_as_half((unsigned short)(e >> 16)));
    float mid = 0.5f * (lo + hi);   // exact same computation as original mid[]
    // strict > : exact-midpoint ties go to the LOWER index,
    // matching argmin's first-minimum tie-break.
    return (xn > mid) ? hi : lo;
}

__global__ void __launch_bounds__(NTHR, 6)
q4_fused_kernel(const float4* __restrict__ x,
                const float* __restrict__ cb, int n_cb,
                float4* __restrict__ out, int n4) {
    __shared__ unsigned s_tbl[NCELL * 32];   // replicated x32: bank == lane
    __shared__ float s_red[NTHR / 32];
    __shared__ float s_red2[NTHR / 32];
    __shared__ unsigned s_epoch;
    __shared__ int s_last;

    const int tid = blockIdx.x * NTHR + threadIdx.x;
    const int stride = NBLK * NTHR;
    const int lane = threadIdx.x & 31;
    const int warp = threadIdx.x >> 5;

    // ---------------- phase 1: local min/max (unroll 4) ----------------
    float lmin = CUDART_INF_F;
    float lmax = -CUDART_INF_F;

    int i = tid;
    for (; i + 3 * stride < n4; i += 4 * stride) {
        float4 v0 = x[i];
        float4 v1 = x[i + stride];
        float4 v2 = x[i + 2 * stride];
        float4 v3 = x[i + 3 * stride];
        float mn0 = fminf(fminf(v0.x, v0.y), fminf(v0.z, v0.w));
        float mx0 = fmaxf(fmaxf(v0.x, v0.y), fmaxf(v0.z, v0.w));
        float mn1 = fminf(fminf(v1.x, v1.y), fminf(v1.z, v1.w));
        float mx1 = fmaxf(fmaxf(v1.x, v1.y), fmaxf(v1.z, v1.w));
        float mn2 = fminf(fminf(v2.x, v2.y), fminf(v2.z, v2.w));
        float mx2 = fmaxf(fmaxf(v2.x, v2.y), fmaxf(v2.z, v2.w));
        float mn3 = fminf(fminf(v3.x, v3.y), fminf(v3.z, v3.w));
        float mx3 = fmaxf(fmaxf(v3.x, v3.y), fmaxf(v3.z, v3.w));
        lmin = fminf(lmin, fminf(fminf(mn0, mn1), fminf(mn2, mn3)));
        lmax = fmaxf(lmax, fmaxf(fmaxf(mx0, mx1), fmaxf(mx2, mx3)));
    }
    for (; i < n4; i += stride) {
        float4 v = x[i];
        lmin = fminf(lmin, fminf(fminf(v.x, v.y), fminf(v.z, v.w)));
        lmax = fmaxf(lmax, fmaxf(fmaxf(v.x, v.y), fmaxf(v.z, v.w)));
    }

    #pragma unroll
    for (int o = 16; o > 0; o >>= 1) {
        lmin = fminf(lmin, __shfl_xor_sync(0xFFFFFFFFu, lmin, o));
        lmax = fmaxf(lmax, __shfl_xor_sync(0xFFFFFFFFu, lmax, o));
    }
    if (lane == 0) { s_red[warp] = lmin; s_red2[warp] = lmax; }
    __syncthreads();

    if (threadIdx.x == 0) {
        float bmin = s_red[0], bmax = s_red2[0];
        #pragma unroll
        for (int w = 1; w < NTHR / 32; w++) {
            bmin = fminf(bmin, s_red[w]);
            bmax = fmaxf(bmax, s_red2[w]);
        }
        g_pmin[blockIdx.x] = bmin;
        g_pmax[blockIdx.x] = bmax;
        __threadfence();
        unsigned old = atomicAdd(&g_counter, 1u);
        s_epoch = old / NBLK;
        s_last = ((old % NBLK) == NBLK - 1);
    }
    __syncthreads();

    const unsigned epoch = s_epoch;

    if (s_last) {
        float bmin = CUDART_INF_F, bmax = -CUDART_INF_F;
        for (int j = threadIdx.x; j < NBLK; j += NTHR) {
            bmin = fminf(bmin, g_pmin[j]);
            bmax = fmaxf(bmax, g_pmax[j]);
        }
        #pragma unroll
        for (int o = 16; o > 0; o >>= 1) {
            bmin = fminf(bmin, __shfl_xor_sync(0xFFFFFFFFu, bmin, o));
            bmax = fmaxf(bmax, __shfl_xor_sync(0xFFFFFFFFu, bmax, o));
        }
        if (lane == 0) { s_red[warp] = bmin; s_red2[warp] = bmax; }
        __syncthreads();
        if (threadIdx.x == 0) {
            float fmn = s_red[0], fmx = s_red2[0];
            #pragma unroll
            for (int w = 1; w < NTHR / 32; w++) {
                fmn = fminf(fmn, s_red[w]);
                fmx = fmaxf(fmx, s_red2[w]);
            }
            g_final_min = fmn;
            g_final_max = fmx;
            __threadfence();
            atomicAdd(&g_release, 1u);
        }
        __syncthreads();
    } else {
        if (threadIdx.x == 0) {
            while (*((volatile unsigned*)&g_release) < epoch + 1u)
                __nanosleep(64);
        }
        __syncthreads();
    }
    __threadfence();  // acquire for g_final_min/max

    const float xmin = g_final_min;
    const float xmax = g_final_max;
    const float inv = 1.0f / (xmax - xmin);

    // ------------- build the replicated 4B/cell interval LUT -------------
    {
        float c[MAX_CB];
        #pragma unroll
        for (int k = 0; k < MAX_CB; k++)
            c[k] = (k < n_cb) ? cb[k] : CUDART_INF_F;
        float mid[MAX_CB - 1];
        #pragma unroll
        for (int j = 0; j < MAX_CB - 1; j++)
            mid[j] = (j + 1 < n_cb) ? 0.5f * (c[j] + c[j + 1]) : CUDART_INF_F;

        for (int e = threadIdx.x; e < NCELL * 32; e += NTHR) {
            int cell = e >> 5;
            float xc = ((float)cell + 0.5f) * (2.0f / NCELL) - 1.0f;
            float val = c[0];
            #pragma unroll
            for (int j = 0; j < MAX_CB - 1; j++)
                val = (xc > mid[j]) ? c[j + 1] : val;
            __half2 pr = __floats2half2_rn(val, val);  // exact: fp16-originated
            s_tbl[e] = *(unsigned*)&pr;
        }
        __syncthreads();

        if (threadIdx.x < n_cb - 1) {
            int cell = cell_of(mid[threadIdx.x]);
            __half2 pr = __floats2half2_rn(c[threadIdx.x], c[threadIdx.x + 1]);
            unsigned pk = *(unsigned*)&pr;
            #pragma unroll
            for (int r = 0; r < 32; r++)
                s_tbl[(cell << 5) | r] = pk;
        }
        __syncthreads();
    }

    // ---------------- phase 2: quantize via LUT, unroll 2 ----------------
    int p = tid;
    for (; p + stride < n4; p += 2 * stride) {
        float4 v0 = x[p];
        float4 v1 = x[p + stride];
        float a0[4] = {v0.x, v0.y, v0.z, v0.w};
        float a1[4] = {v1.x, v1.y, v1.z, v1.w};
        float r0[4], r1[4];
        #pragma unroll
        for (int k = 0; k < 4; k++) {
            float xn0 = fmaf((a0[k] - xmin) * inv, 2.0f, -1.0f);
            float xn1 = fmaf((a1[k] - xmin) * inv, 2.0f, -1.0f);
            unsigned e0 = s_tbl[(cell_of(xn0) << 5) | lane];
            unsigned e1 = s_tbl[(cell_of(xn1) << 5) | lane];
            r0[k] = lut_pick(e0, xn0);
            r1[k] = lut_pick(e1, xn1);
        }
        __stcs(&out[p], make_float4(r0[0], r0[1], r0[2], r0[3]));
        __stcs(&out[p + stride], make_float4(r1[0], r1[1], r1[2], r1[3]));
    }
    for (; p < n4; p += stride) {
        float4 v = x[p];
        float a0[4] = {v.x, v.y, v.z, v.w};
        float r0[4];
        #pragma unroll
        for (int k = 0; k < 4; k++) {
            float xn = fmaf((a0[k] - xmin) * inv, 2.0f, -1.0f);
            unsigned e = s_tbl[(cell_of(xn) << 5) | lane];
            r0[k] = lut_pick(e, xn);
        }
        __stcs(&out[p], make_float4(r0[0], r0[1], r0[2], r0[3]));
    }
}

extern "C" void kernel_launch(void* const* d_in, const int* in_sizes, int n_in,
                              void* d_out, int out_size) {
    const float4* x = (const float4*)d_in[0];
    const float* cb = (const float*)d_in[1];
    float4* out = (float4*)d_out;

    int n = in_sizes[0];      // 8388608
    int n_cb = in_sizes[1];   // 14
    if (n_cb > MAX_CB) n_cb = MAX_CB;
    int n4 = n >> 2;

    q4_fused_kernel<<<NBLK, NTHR>>>(x, cb, n_cb, out, n4);
}

// round 9
// speedup vs baseline: 1.4278x; 1.4278x over previous
#include <cuda_runtime.h>
#include <cuda_fp16.h>
#include <math_constants.h>

// ---------------------------------------------------------------------------
// Quantization4bit, single persistent kernel:
//   phase 1: per-block min/max partials (grid-stride, float4, unroll-4)
//   grid barrier: monotonic counter/epoch (replay-safe)
//   phase 2: affine normalize + nearest-codebook via a 256-cell, 8-byte/cell
//            shared-memory interval LUT: {mid fp32, half2(c_lo,c_hi)}.
//            fp16-originated values round-trip exactly; compare in fp32 =>
//            bit-identical to the 14-deep midpoint select chain
//            (fp32 |.| argmin, first-min tie-break).
// 740 blocks x 256 thr, 5 blocks/SM co-resident (launch_bounds) => barrier ok.
// ---------------------------------------------------------------------------

#define MAX_CB 16
#define NBLK 740
#define NTHR 256
#define NCELL 256

__device__ float g_pmin[NBLK];
__device__ float g_pmax[NBLK];
__device__ float g_final_min;
__device__ float g_final_max;
__device__ unsigned g_counter = 0;   // monotonic arrivals (never reset)
__device__ unsigned g_release = 0;   // monotonic release epoch

__device__ __forceinline__ int cell_of(float xn) {
    float u = fmaf(xn, (float)(NCELL / 2), (float)(NCELL / 2));  // >= 0 by construction
    u = fminf(u, (float)(NCELL - 1));
    return (int)u;
}

__device__ __forceinline__ float lut_pick(uint2 e, float xn) {
    float midv = __uint_as_float(e.x);
    // strict > : exact-midpoint ties go to the LOWER index (low half),
    // matching argmin's first-minimum tie-break.
    unsigned bits = (xn > midv) ? (e.y >> 16) : (e.y & 0xFFFFu);
    return __half2float(__ushort_as_half((unsigned short)bits));
}

__global__ void __launch_bounds__(NTHR, 5)
q4_fused_kernel(const float4* __restrict__ x,
                const float* __restrict__ cb, int n_cb,
                float4* __restrict__ out, int n4) {
    __shared__ uint2 s_tbl[NCELL];       // {mid fp32 bits, half2(c_lo,c_hi)}
    __shared__ float s_red[NTHR / 32];
    __shared__ float s_red2[NTHR / 32];
    __shared__ unsigned s_epoch;
    __shared__ int s_last;

    const int tid = blockIdx.x * NTHR + threadIdx.x;
    const int stride = NBLK * NTHR;
    const int lane = threadIdx.x & 31;
    const int warp = threadIdx.x >> 5;

    // ---------------- phase 1: local min/max (unroll 4) ----------------
    float lmin = CUDART_INF_F;
    float lmax = -CUDART_INF_F;

    int i = tid;
    for (; i + 3 * stride < n4; i += 4 * stride) {
        float4 v0 = x[i];
        float4 v1 = x[i + stride];
        float4 v2 = x[i + 2 * stride];
        float4 v3 = x[i + 3 * stride];
        float mn0 = fminf(fminf(v0.x, v0.y), fminf(v0.z, v0.w));
        float mx0 = fmaxf(fmaxf(v0.x, v0.y), fmaxf(v0.z, v0.w));
        float mn1 = fminf(fminf(v1.x, v1.y), fminf(v1.z, v1.w));
        float mx1 = fmaxf(fmaxf(v1.x, v1.y), fmaxf(v1.z, v1.w));
        float mn2 = fminf(fminf(v2.x, v2.y), fminf(v2.z, v2.w));
        float mx2 = fmaxf(fmaxf(v2.x, v2.y), fmaxf(v2.z, v2.w));
        float mn3 = fminf(fminf(v3.x, v3.y), fminf(v3.z, v3.w));
        float mx3 = fmaxf(fmaxf(v3.x, v3.y), fmaxf(v3.z, v3.w));
        lmin = fminf(lmin, fminf(fminf(mn0, mn1), fminf(mn2, mn3)));
        lmax = fmaxf(lmax, fmaxf(fmaxf(mx0, mx1), fmaxf(mx2, mx3)));
    }
    for (; i < n4; i += stride) {
        float4 v = x[i];
        lmin = fminf(lmin, fminf(fminf(v.x, v.y), fminf(v.z, v.w)));
        lmax = fmaxf(lmax, fmaxf(fmaxf(v.x, v.y), fmaxf(v.z, v.w)));
    }

    #pragma unroll
    for (int o = 16; o > 0; o >>= 1) {
        lmin = fminf(lmin, __shfl_xor_sync(0xFFFFFFFFu, lmin, o));
        lmax = fmaxf(lmax, __shfl_xor_sync(0xFFFFFFFFu, lmax, o));
    }
    if (lane == 0) { s_red[warp] = lmin; s_red2[warp] = lmax; }
    __syncthreads();

    if (threadIdx.x == 0) {
        float bmin = s_red[0], bmax = s_red2[0];
        #pragma unroll
        for (int w = 1; w < NTHR / 32; w++) {
            bmin = fminf(bmin, s_red[w]);
            bmax = fmaxf(bmax, s_red2[w]);
        }
        g_pmin[blockIdx.x] = bmin;
        g_pmax[blockIdx.x] = bmax;
        __threadfence();
        unsigned old = atomicAdd(&g_counter, 1u);
        s_epoch = old / NBLK;
        s_last = ((old % NBLK) == NBLK - 1);
    }
    __syncthreads();

    const unsigned epoch = s_epoch;

    if (s_last) {
        float bmin = CUDART_INF_F, bmax = -CUDART_INF_F;
        for (int j = threadIdx.x; j < NBLK; j += NTHR) {
            bmin = fminf(bmin, g_pmin[j]);
            bmax = fmaxf(bmax, g_pmax[j]);
        }
        #pragma unroll
        for (int o = 16; o > 0; o >>= 1) {
            bmin = fminf(bmin, __shfl_xor_sync(0xFFFFFFFFu, bmin, o));
            bmax = fmaxf(bmax, __shfl_xor_sync(0xFFFFFFFFu, bmax, o));
        }
        if (lane == 0) { s_red[warp] = bmin; s_red2[warp] = bmax; }
        __syncthreads();
        if (threadIdx.x == 0) {
            float fmn = s_red[0], fmx = s_red2[0];
            #pragma unroll
            for (int w = 1; w < NTHR / 32; w++) {
                fmn = fminf(fmn, s_red[w]);
                fmx = fmaxf(fmx, s_red2[w]);
            }
            g_final_min = fmn;
            g_final_max = fmx;
            __threadfence();
            atomicAdd(&g_release, 1u);
        }
        __syncthreads();
    } else {
        if (threadIdx.x == 0) {
            while (*((volatile unsigned*)&g_release) < epoch + 1u)
                __nanosleep(64);
        }
        __syncthreads();
    }
    __threadfence();  // acquire for g_final_min/max

    const float xmin = g_final_min;
    const float xmax = g_final_max;
    const float inv = 1.0f / (xmax - xmin);

    // ------------- build the 8B/cell interval LUT (256 entries) -------------
    {
        float c[MAX_CB];
        #pragma unroll
        for (int k = 0; k < MAX_CB; k++)
            c[k] = (k < n_cb) ? cb[k] : CUDART_INF_F;
        float mid[MAX_CB - 1];
        #pragma unroll
        for (int j = 0; j < MAX_CB - 1; j++)
            mid[j] = (j + 1 < n_cb) ? 0.5f * (c[j] + c[j + 1]) : CUDART_INF_F;

        for (int cell = threadIdx.x; cell < NCELL; cell += NTHR) {
            float xc = ((float)cell + 0.5f) * (2.0f / NCELL) - 1.0f;
            float val = c[0];
            #pragma unroll
            for (int j = 0; j < MAX_CB - 1; j++)
                val = (xc > mid[j]) ? c[j + 1] : val;
            __half2 pr = __floats2half2_rn(val, val);  // exact: fp16-originated
            s_tbl[cell] = make_uint2(__float_as_uint(CUDART_INF_F),
                                     *(unsigned*)&pr);
        }
        __syncthreads();

        if (threadIdx.x < n_cb - 1) {
            float mj = mid[threadIdx.x];
            int cell = cell_of(mj);
            __half2 pr = __floats2half2_rn(c[threadIdx.x], c[threadIdx.x + 1]);
            s_tbl[cell] = make_uint2(__float_as_uint(mj), *(unsigned*)&pr);
        }
        __syncthreads();
    }

    // ---------------- phase 2: quantize via LUT, unroll 2 ----------------
    int p = tid;
    for (; p + stride < n4; p += 2 * stride) {
        float4 v0 = x[p];
        float4 v1 = x[p + stride];
        float a0[4] = {v0.x, v0.y, v0.z, v0.w};
        float a1[4] = {v1.x, v1.y, v1.z, v1.w};
        float r0[4], r1[4];
        #pragma unroll
        for (int k = 0; k < 4; k++) {
            float xn0 = fmaf((a0[k] - xmin) * inv, 2.0f, -1.0f);
            float xn1 = fmaf((a1[k] - xmin) * inv, 2.0f, -1.0f);
            uint2 e0 = s_tbl[cell_of(xn0)];
            uint2 e1 = s_tbl[cell_of(xn1)];
            r0[k] = lut_pick(e0, xn0);
            r1[k] = lut_pick(e1, xn1);
        }
        __stcs(&out[p], make_float4(r0[0], r0[1], r0[2], r0[3]));
        __stcs(&out[p + stride], make_float4(r1[0], r1[1], r1[2], r1[3]));
    }
    for (; p < n4; p += stride) {
        float4 v = x[p];
        float a0[4] = {v.x, v.y, v.z, v.w};
        float r0[4];
        #pragma unroll
        for (int k = 0; k < 4; k++) {
            float xn = fmaf((a0[k] - xmin) * inv, 2.0f, -1.0f);
            uint2 e = s_tbl[cell_of(xn)];
            r0[k] = lut_pick(e, xn);
        }
        __stcs(&out[p], make_float4(r0[0], r0[1], r0[2], r0[3]));
    }
}

extern "C" void kernel_launch(void* const* d_in, const int* in_sizes, int n_in,
                              void* d_out, int out_size) {
    const float4* x = (const float4*)d_in[0];
    const float* cb = (const float*)d_in[1];
    float4* out = (float4*)d_out;

    int n = in_sizes[0];      // 8388608
    int n_cb = in_sizes[1];   // 14
    if (n_cb > MAX_CB) n_cb = MAX_CB;
    int n4 = n >> 2;

    q4_fused_kernel<<<NBLK, NTHR>>>(x, cb, n_cb, out, n4);
}

// round 10
// speedup vs baseline: 1.4682x; 1.0283x over previous
#include <cuda_runtime.h>
#include <cuda_fp16.h>
#include <math_constants.h>

// ---------------------------------------------------------------------------
// Quantization4bit, single persistent kernel:
//   phase 1: per-block min/max partials (grid-stride, float4 __ldcg, unroll-4)
//   grid barrier: monotonic counter/epoch (replay-safe)
//   phase 2: affine normalize + nearest-codebook via a 256-cell, 8-byte/cell
//            shared-memory interval LUT: {mid fp32, half2(c_lo,c_hi)}.
//            fp16-originated values round-trip exactly; compare in fp32 =>
//            bit-identical to the 14-deep midpoint select chain
//            (fp32 |.| argmin, first-min tie-break). Unroll-4 for MLP;
//            __ldcg keeps x out of L1 (L2-hot), __stcs streams the output.
// 592 blocks x 256 thr, 4 blocks/SM co-resident (launch_bounds) => barrier ok.
// ---------------------------------------------------------------------------

#define MAX_CB 16
#define NBLK 592
#define NTHR 256
#define NCELL 256

__device__ float g_pmin[NBLK];
__device__ float g_pmax[NBLK];
__device__ float g_final_min;
__device__ float g_final_max;
__device__ unsigned g_counter = 0;   // monotonic arrivals (never reset)
__device__ unsigned g_release = 0;   // monotonic release epoch

__device__ __forceinline__ int cell_of(float xn) {
    float u = fmaf(xn, (float)(NCELL / 2), (float)(NCELL / 2));  // >= 0 by construction
    u = fminf(u, (float)(NCELL - 1));
    return (int)u;
}

__device__ __forceinline__ float lut_pick(uint2 e, float xn) {
    float midv = __uint_as_float(e.x);
    // strict > : exact-midpoint ties go to the LOWER index (low half),
    // matching argmin's first-minimum tie-break.
    unsigned bits = (xn > midv) ? (e.y >> 16) : (e.y & 0xFFFFu);
    return __half2float(__ushort_as_half((unsigned short)bits));
}

__device__ __forceinline__ void mm4(float4 v, float& mn, float& mx) {
    mn = fminf(mn, fminf(fminf(v.x, v.y), fminf(v.z, v.w)));
    mx = fmaxf(mx, fmaxf(fmaxf(v.x, v.y), fmaxf(v.z, v.w)));
}

__device__ __forceinline__ float4 quant4(float4 v, float xmin, float inv,
                                         const uint2* s_tbl) {
    float a[4] = {v.x, v.y, v.z, v.w};
    float r[4];
    #pragma unroll
    for (int k = 0; k < 4; k++) {
        float xn = fmaf((a[k] - xmin) * inv, 2.0f, -1.0f);
        uint2 e = s_tbl[cell_of(xn)];
        r[k] = lut_pick(e, xn);
    }
    return make_float4(r[0], r[1], r[2], r[3]);
}

__global__ void __launch_bounds__(NTHR, 4)
q4_fused_kernel(const float4* __restrict__ x,
                const float* __restrict__ cb, int n_cb,
                float4* __restrict__ out, int n4) {
    __shared__ uint2 s_tbl[NCELL];       // {mid fp32 bits, half2(c_lo,c_hi)}
    __shared__ float s_red[NTHR / 32];
    __shared__ float s_red2[NTHR / 32];
    __shared__ unsigned s_epoch;
    __shared__ int s_last;

    const int tid = blockIdx.x * NTHR + threadIdx.x;
    const int stride = NBLK * NTHR;
    const int lane = threadIdx.x & 31;
    const int warp = threadIdx.x >> 5;

    // ---------------- phase 1: local min/max (unroll 4, .cg loads) --------
    float lmin = CUDART_INF_F;
    float lmax = -CUDART_INF_F;

    int i = tid;
    for (; i + 3 * stride < n4; i += 4 * stride) {
        float4 v0 = __ldcg(&x[i]);
        float4 v1 = __ldcg(&x[i + stride]);
        float4 v2 = __ldcg(&x[i + 2 * stride]);
        float4 v3 = __ldcg(&x[i + 3 * stride]);
        mm4(v0, lmin, lmax);
        mm4(v1, lmin, lmax);
        mm4(v2, lmin, lmax);
        mm4(v3, lmin, lmax);
    }
    for (; i < n4; i += stride) {
        float4 v = __ldcg(&x[i]);
        mm4(v, lmin, lmax);
    }

    #pragma unroll
    for (int o = 16; o > 0; o >>= 1) {
        lmin = fminf(lmin, __shfl_xor_sync(0xFFFFFFFFu, lmin, o));
        lmax = fmaxf(lmax, __shfl_xor_sync(0xFFFFFFFFu, lmax, o));
    }
    if (lane == 0) { s_red[warp] = lmin; s_red2[warp] = lmax; }
    __syncthreads();

    if (threadIdx.x == 0) {
        float bmin = s_red[0], bmax = s_red2[0];
        #pragma unroll
        for (int w = 1; w < NTHR / 32; w++) {
            bmin = fminf(bmin, s_red[w]);
            bmax = fmaxf(bmax, s_red2[w]);
        }
        g_pmin[blockIdx.x] = bmin;
        g_pmax[blockIdx.x] = bmax;
        __threadfence();
        unsigned old = atomicAdd(&g_counter, 1u);
        s_epoch = old / NBLK;
        s_last = ((old % NBLK) == NBLK - 1);
    }
    __syncthreads();

    const unsigned epoch = s_epoch;

    if (s_last) {
        float bmin = CUDART_INF_F, bmax = -CUDART_INF_F;
        for (int j = threadIdx.x; j < NBLK; j += NTHR) {
            bmin = fminf(bmin, g_pmin[j]);
            bmax = fmaxf(bmax, g_pmax[j]);
        }
        #pragma unroll
        for (int o = 16; o > 0; o >>= 1) {
            bmin = fminf(bmin, __shfl_xor_sync(0xFFFFFFFFu, bmin, o));
            bmax = fmaxf(bmax, __shfl_xor_sync(0xFFFFFFFFu, bmax, o));
        }
        if (lane == 0) { s_red[warp] = bmin; s_red2[warp] = bmax; }
        __syncthreads();
        if (threadIdx.x == 0) {
            float fmn = s_red[0], fmx = s_red2[0];
            #pragma unroll
            for (int w = 1; w < NTHR / 32; w++) {
                fmn = fminf(fmn, s_red[w]);
                fmx = fmaxf(fmx, s_red2[w]);
            }
            g_final_min = fmn;
            g_final_max = fmx;
            __threadfence();
            atomicAdd(&g_release, 1u);
        }
        __syncthreads();
    } else {
        if (threadIdx.x == 0) {
            while (*((volatile unsigned*)&g_release) < epoch + 1u)
                __nanosleep(64);
        }
        __syncthreads();
    }
    __threadfence();  // acquire for g_final_min/max

    const float xmin = g_final_min;
    const float xmax = g_final_max;
    const float inv = 1.0f / (xmax - xmin);

    // ------------- build the 8B/cell interval LUT (256 entries) -----------
    {
        float c[MAX_CB];
        #pragma unroll
        for (int k = 0; k < MAX_CB; k++)
            c[k] = (k < n_cb) ? cb[k] : CUDART_INF_F;
        float mid[MAX_CB - 1];
        #pragma unroll
        for (int j = 0; j < MAX_CB - 1; j++)
            mid[j] = (j + 1 < n_cb) ? 0.5f * (c[j] + c[j + 1]) : CUDART_INF_F;

        for (int cell = threadIdx.x; cell < NCELL; cell += NTHR) {
            float xc = ((float)cell + 0.5f) * (2.0f / NCELL) - 1.0f;
            float val = c[0];
            #pragma unroll
            for (int j = 0; j < MAX_CB - 1; j++)
                val = (xc > mid[j]) ? c[j + 1] : val;
            __half2 pr = __floats2half2_rn(val, val);  // exact: fp16-originated
            s_tbl[cell] = make_uint2(__float_as_uint(CUDART_INF_F),
                                     *(unsigned*)&pr);
        }
        __syncthreads();

        if (threadIdx.x < n_cb - 1) {
            float mj = mid[threadIdx.x];
            int cell = cell_of(mj);
            __half2 pr = __floats2half2_rn(c[threadIdx.x], c[threadIdx.x + 1]);
            s_tbl[cell] = make_uint2(__float_as_uint(mj), *(unsigned*)&pr);
        }
        __syncthreads();
    }

    // ---------------- phase 2: quantize via LUT, unroll 4 ----------------
    int p = tid;
    for (; p + 3 * stride < n4; p += 4 * stride) {
        float4 v0 = __ldcg(&x[p]);
        float4 v1 = __ldcg(&x[p + stride]);
        float4 v2 = __ldcg(&x[p + 2 * stride]);
        float4 v3 = __ldcg(&x[p + 3 * stride]);
        float4 r0 = quant4(v0, xmin, inv, s_tbl);
        float4 r1 = quant4(v1, xmin, inv, s_tbl);
        float4 r2 = quant4(v2, xmin, inv, s_tbl);
        float4 r3 = quant4(v3, xmin, inv, s_tbl);
        __stcs(&out[p], r0);
        __stcs(&out[p + stride], r1);
        __stcs(&out[p + 2 * stride], r2);
        __stcs(&out[p + 3 * stride], r3);
    }
    for (; p < n4; p += stride) {
        float4 v = __ldcg(&x[p]);
        __stcs(&out[p], quant4(v, xmin, inv, s_tbl));
    }
}

extern "C" void kernel_launch(void* const* d_in, const int* in_sizes, int n_in,
                              void* d_out, int out_size) {
    const float4* x = (const float4*)d_in[0];
    const float* cb = (const float*)d_in[1];
    float4* out = (float4*)d_out;

    int n = in_sizes[0];      // 8388608
    int n_cb = in_sizes[1];   // 14
    if (n_cb > MAX_CB) n_cb = MAX_CB;
    int n4 = n >> 2;

    q4_fused_kernel<<<NBLK, NTHR>>>(x, cb, n_cb, out, n4);
}

// round 11
// speedup vs baseline: 1.7593x; 1.1983x over previous
#include <cuda_runtime.h>
#include <cuda_fp16.h>
#include <math_constants.h>

// ---------------------------------------------------------------------------
// Quantization4bit, single persistent kernel:
//   phase 1: per-block min/max partials (grid-stride, float4 __ldcg, unroll-4)
//   grid barrier: monotonic counter/epoch (replay-safe)
//   phase 2: affine normalize + nearest-codebook via a 256-cell LUT of
//            half2(c_lo, c_hi), replicated x32 at s[cell*32+lane] so every
//            gather is bank-conflict-free regardless of data distribution.
//            Build is copy-based: 256 chain evaluations + lane-rotated
//            conflict-free replication (cheap, unlike R8).
//            Midpoint recomputed as 0.5f*(f32(lo)+f32(hi)) -- identical fp32
//            ops/inputs as the reference chain => bit-exact
//            (fp32 |.| argmin, first-min tie-break).
// 592 blocks x 256 thr, 4 blocks/SM co-resident (launch_bounds, 32KB smem
// x4 = 128KB/SM <= 228KB) => spin barrier safe.
// ---------------------------------------------------------------------------

#define MAX_CB 16
#define NBLK 592
#define NTHR 256
#define NCELL 256

__device__ float g_pmin[NBLK];
__device__ float g_pmax[NBLK];
__device__ float g_final_min;
__device__ float g_final_max;
__device__ unsigned g_counter = 0;   // monotonic arrivals (never reset)
__device__ unsigned g_release = 0;   // monotonic release epoch

__device__ __forceinline__ int cell_of(float xn) {
    float u = fmaf(xn, (float)(NCELL / 2), (float)(NCELL / 2));  // >= 0 by construction
    u = fminf(u, (float)(NCELL - 1));
    return (int)u;
}

__device__ __forceinline__ float lut_pick(unsigned e, float xn) {
    float lo = __half2float(__ushort_as_half((unsigned short)(e & 0xFFFFu)));
    float hi = __half2float(__ushort_as_half((unsigned short)(e >> 16)));
    float mid = 0.5f * (lo + hi);   // exact same computation as reference mid[]
    // strict > : exact-midpoint ties go to the LOWER index,
    // matching argmin's first-minimum tie-break.
    return (xn > mid) ? hi : lo;
}

__device__ __forceinline__ void mm4(float4 v, float& mn, float& mx) {
    mn = fminf(mn, fminf(fminf(v.x, v.y), fminf(v.z, v.w)));
    mx = fmaxf(mx, fmaxf(fmaxf(v.x, v.y), fmaxf(v.z, v.w)));
}

__device__ __forceinline__ float4 quant4(float4 v, float xmin, float inv,
                                         const unsigned* s_tbl, int lane) {
    float a[4] = {v.x, v.y, v.z, v.w};
    float r[4];
    #pragma unroll
    for (int k = 0; k < 4; k++) {
        float xn = fmaf((a[k] - xmin) * inv, 2.0f, -1.0f);
        unsigned e = s_tbl[(cell_of(xn) << 5) | lane];   // bank == lane
        r[k] = lut_pick(e, xn);
    }
    return make_float4(r[0], r[1], r[2], r[3]);
}

__global__ void __launch_bounds__(NTHR, 4)
q4_fused_kernel(const float4* __restrict__ x,
                const float* __restrict__ cb, int n_cb,
                float4* __restrict__ out, int n4) {
    __shared__ unsigned s_tbl[NCELL * 32];   // x32 replicated, bank == lane
    __shared__ float s_red[NTHR / 32];
    __shared__ float s_red2[NTHR / 32];
    __shared__ unsigned s_epoch;
    __shared__ int s_last;

    const int tid = blockIdx.x * NTHR + threadIdx.x;
    const int stride = NBLK * NTHR;
    const int lane = threadIdx.x & 31;
    const int warp = threadIdx.x >> 5;

    // ---------------- phase 1: local min/max (unroll 4, .cg loads) --------
    float lmin = CUDART_INF_F;
    float lmax = -CUDART_INF_F;

    int i = tid;
    for (; i + 3 * stride < n4; i += 4 * stride) {
        float4 v0 = __ldcg(&x[i]);
        float4 v1 = __ldcg(&x[i + stride]);
        float4 v2 = __ldcg(&x[i + 2 * stride]);
        float4 v3 = __ldcg(&x[i + 3 * stride]);
        mm4(v0, lmin, lmax);
        mm4(v1, lmin, lmax);
        mm4(v2, lmin, lmax);
        mm4(v3, lmin, lmax);
    }
    for (; i < n4; i += stride) {
        float4 v = __ldcg(&x[i]);
        mm4(v, lmin, lmax);
    }

    #pragma unroll
    for (int o = 16; o > 0; o >>= 1) {
        lmin = fminf(lmin, __shfl_xor_sync(0xFFFFFFFFu, lmin, o));
        lmax = fmaxf(lmax, __shfl_xor_sync(0xFFFFFFFFu, lmax, o));
    }
    if (lane == 0) { s_red[warp] = lmin; s_red2[warp] = lmax; }
    __syncthreads();

    if (threadIdx.x == 0) {
        float bmin = s_red[0], bmax = s_red2[0];
        #pragma unroll
        for (int w = 1; w < NTHR / 32; w++) {
            bmin = fminf(bmin, s_red[w]);
            bmax = fmaxf(bmax, s_red2[w]);
        }
        g_pmin[blockIdx.x] = bmin;
        g_pmax[blockIdx.x] = bmax;
        __threadfence();
        unsigned old = atomicAdd(&g_counter, 1u);
        s_epoch = old / NBLK;
        s_last = ((old % NBLK) == NBLK - 1);
    }
    __syncthreads();

    const unsigned epoch = s_epoch;

    if (s_last) {
        float bmin = CUDART_INF_F, bmax = -CUDART_INF_F;
        for (int j = threadIdx.x; j < NBLK; j += NTHR) {
            bmin = fminf(bmin, g_pmin[j]);
            bmax = fmaxf(bmax, g_pmax[j]);
        }
        #pragma unroll
        for (int o = 16; o > 0; o >>= 1) {
            bmin = fminf(bmin, __shfl_xor_sync(0xFFFFFFFFu, bmin, o));
            bmax = fmaxf(bmax, __shfl_xor_sync(0xFFFFFFFFu, bmax, o));
        }
        if (lane == 0) { s_red[warp] = bmin; s_red2[warp] = bmax; }
        __syncthreads();
        if (threadIdx.x == 0) {
            float fmn = s_red[0], fmx = s_red2[0];
            #pragma unroll
            for (int w = 1; w < NTHR / 32; w++) {
                fmn = fminf(fmn, s_red[w]);
                fmx = fmaxf(fmx, s_red2[w]);
            }
            g_final_min = fmn;
            g_final_max = fmx;
            __threadfence();
            atomicAdd(&g_release, 1u);
        }
        __syncthreads();
    } else {
        if (threadIdx.x == 0) {
            while (*((volatile unsigned*)&g_release) < epoch + 1u)
                __nanosleep(64);
        }
        __syncthreads();
    }
    __threadfence();  // acquire for g_final_min/max

    const float xmin = g_final_min;
    const float xmax = g_final_max;
    const float inv = 1.0f / (xmax - xmin);

    // ------- build the x32-replicated 4B/cell LUT (copy-based, cheap) -----
    {
        float c[MAX_CB];
        #pragma unroll
        for (int k = 0; k < MAX_CB; k++)
            c[k] = (k < n_cb) ? cb[k] : CUDART_INF_F;
        float mid[MAX_CB - 1];
        #pragma unroll
        for (int j = 0; j < MAX_CB - 1; j++)
            mid[j] = (j + 1 < n_cb) ? 0.5f * (c[j] + c[j + 1]) : CUDART_INF_F;

        // each thread owns exactly one cell (NTHR == NCELL)
        int cell = threadIdx.x;
        float xc = ((float)cell + 0.5f) * (2.0f / NCELL) - 1.0f;
        float val = c[0];
        #pragma unroll
        for (int j = 0; j < MAX_CB - 1; j++)
            val = (xc > mid[j]) ? c[j + 1] : val;
        float lo = val, hi = val;

        // if a midpoint falls in this cell, store (c_lo, c_hi) instead
        #pragma unroll
        for (int j = 0; j < MAX_CB - 1; j++) {
            if (j + 1 < n_cb && cell_of(mid[j]) == cell) {
                lo = c[j];
                hi = c[j + 1];
            }
        }
        __half2 pr = __floats2half2_rn(lo, hi);  // exact: fp16-originated
        unsigned pk = *(unsigned*)&pr;

        // lane-rotated replication: for fixed r, banks are all distinct
        #pragma unroll
        for (int r = 0; r < 32; r++)
            s_tbl[(cell << 5) | ((r + lane) & 31)] = pk;
        __syncthreads();
    }

    // ---------------- phase 2: quantize via LUT, unroll 4 ----------------
    int p = tid;
    for (; p + 3 * stride < n4; p += 4 * stride) {
        float4 v0 = __ldcg(&x[p]);
        float4 v1 = __ldcg(&x[p + stride]);
        float4 v2 = __ldcg(&x[p + 2 * stride]);
        float4 v3 = __ldcg(&x[p + 3 * stride]);
        float4 r0 = quant4(v0, xmin, inv, s_tbl, lane);
        float4 r1 = quant4(v1, xmin, inv, s_tbl, lane);
        float4 r2 = quant4(v2, xmin, inv, s_tbl, lane);
        float4 r3 = quant4(v3, xmin, inv, s_tbl, lane);
        __stcs(&out[p], r0);
        __stcs(&out[p + stride], r1);
        __stcs(&out[p + 2 * stride], r2);
        __stcs(&out[p + 3 * stride], r3);
    }
    for (; p < n4; p += stride) {
        float4 v = __ldcg(&x[p]);
        __stcs(&out[p], quant4(v, xmin, inv, s_tbl, lane));
    }
}

extern "C" void kernel_launch(void* const* d_in, const int* in_sizes, int n_in,
                              void* d_out, int out_size) {
    const float4* x = (const float4*)d_in[0];
    const float* cb = (const float*)d_in[1];
    float4* out = (float4*)d_out;

    int n = in_sizes[0];      // 8388608
    int n_cb = in_sizes[1];   // 14
    if (n_cb > MAX_CB) n_cb = MAX_CB;
    int n4 = n >> 2;

    q4_fused_kernel<<<NBLK, NTHR>>>(x, cb, n_cb, out, n4);
}